// round 5
// baseline (speedup 1.0000x reference)
#include <cuda_runtime.h>
#include <cuda_bf16.h>

// SingleRoIExtractor: FPN RoIAlign (aligned=False), out 7x7, sr=2.
// R3: R1 parallel shape (thread per output element), but sample geometry
// computed once per block into shared; branchless; 16 LDGs batched; __stcs.

#define OUTS   7
#define CH     256
#define BINS   (OUTS * OUTS)            // 49
#define PER_ROI (CH * BINS)             // 12544
#define BLK    256
#define BLOCKS_PER_ROI (PER_ROI / BLK)  // 49
#define NSAMPLES 196                    // 49 bins * 4 samples

struct __align__(16) SampleRec {
    int4   o;   // tap offsets within channel plane
    float4 w;   // tap weights (validity folded in)
};

__global__ void __launch_bounds__(BLK)
roi_extract_kernel(const float* __restrict__ f0,
                   const float* __restrict__ f1,
                   const float* __restrict__ f2,
                   const float* __restrict__ f3,
                   const float* __restrict__ rois,
                   float* __restrict__ out)
{
    __shared__ SampleRec rec[NSAMPLES];
    __shared__ float s_x1, s_y1, s_binw, s_binh;
    __shared__ const float* s_base;
    __shared__ int s_H, s_W;

    const int n   = blockIdx.x / BLOCKS_PER_ROI;
    const int blk = blockIdx.x % BLOCKS_PER_ROI;
    const int t   = threadIdx.x;

    if (t == 0) {
        const float rb  = rois[n * 5 + 0];
        const float rx1 = rois[n * 5 + 1];
        const float ry1 = rois[n * 5 + 2];
        const float rx2 = rois[n * 5 + 3];
        const float ry2 = rois[n * 5 + 4];

        const float sc = sqrtf((rx2 - rx1 + 1.0f) * (ry2 - ry1 + 1.0f));
        int lvl = (int)floorf(log2f(sc * (1.0f / 56.0f) + 1e-6f));
        lvl = lvl < 0 ? 0 : (lvl > 3 ? 3 : lvl);

        const float* f; int H, W; float ss;
        if      (lvl == 0) { f = f0; H = 200; W = 304; ss = 0.25f;    }
        else if (lvl == 1) { f = f1; H = 100; W = 152; ss = 0.125f;   }
        else if (lvl == 2) { f = f2; H = 50;  W = 76;  ss = 0.0625f;  }
        else               { f = f3; H = 25;  W = 38;  ss = 0.03125f; }

        const int b = (int)rb;
        const float x1 = rx1 * ss, y1 = ry1 * ss;
        s_x1 = x1; s_y1 = y1;
        s_binw = fmaxf(rx2 * ss - x1, 1.0f) * (1.0f / OUTS);
        s_binh = fmaxf(ry2 * ss - y1, 1.0f) * (1.0f / OUTS);
        s_base = f + (size_t)b * CH * H * W;
        s_H = H; s_W = W;
    }
    __syncthreads();

    if (t < NSAMPLES) {
        const int bin = t >> 2;
        const int s   = t & 3;
        const int ph  = bin / OUTS;
        const int pw  = bin - ph * OUTS;
        const int iy  = s >> 1;
        const int ix  = s & 1;

        const int H = s_H, W = s_W;
        const float Hf = (float)H, Wf = (float)W;

        const float y = s_y1 + ((float)(ph * 2 + iy) + 0.5f) * 0.5f * s_binh;
        const float x = s_x1 + ((float)(pw * 2 + ix) + 0.5f) * 0.5f * s_binw;
        const bool valid = (y >= -1.0f) & (y <= Hf) & (x >= -1.0f) & (x <= Wf);

        const float yc = fminf(fmaxf(y, 0.0f), Hf - 1.0f);
        const float xc = fminf(fmaxf(x, 0.0f), Wf - 1.0f);
        const int   y0 = (int)yc;
        const int   x0 = (int)xc;
        const float ly = yc - (float)y0;
        const float lx = xc - (float)x0;
        const int   yB = min(y0 + 1, H - 1);
        const int   xB = min(x0 + 1, W - 1);

        const float vmul = valid ? 0.25f : 0.0f;   // fold the 1/4 sample mean in
        const float wy0 = (1.0f - ly) * vmul;
        const float wy1 = ly * vmul;

        SampleRec r;
        r.o = make_int4(y0 * W + x0, y0 * W + xB, yB * W + x0, yB * W + xB);
        r.w = make_float4(wy0 * (1.0f - lx), wy0 * lx,
                          wy1 * (1.0f - lx), wy1 * lx);
        rec[t] = r;
    }
    __syncthreads();

    const int local = blk * BLK + t;
    const int c   = local / BINS;
    const int bin = local - c * BINS;

    const int HW = s_H * s_W;
    const float* __restrict__ fc = s_base + (size_t)c * HW;

    float acc = 0.0f;
    #pragma unroll
    for (int s = 0; s < 4; ++s) {
        const SampleRec r = rec[bin * 4 + s];
        acc += __ldg(fc + r.o.x) * r.w.x
             + __ldg(fc + r.o.y) * r.w.y
             + __ldg(fc + r.o.z) * r.w.z
             + __ldg(fc + r.o.w) * r.w.w;
    }

    __stcs(out + (size_t)n * PER_ROI + local, acc);
}

extern "C" void kernel_launch(void* const* d_in, const int* in_sizes, int n_in,
                              void* d_out, int out_size)
{
    const float* f0   = (const float*)d_in[0];
    const float* f1   = (const float*)d_in[1];
    const float* f2   = (const float*)d_in[2];
    const float* f3   = (const float*)d_in[3];
    const float* rois = (const float*)d_in[4];
    float* out = (float*)d_out;

    const int K = in_sizes[4] / 5;
    roi_extract_kernel<<<K * BLOCKS_PER_ROI, BLK>>>(f0, f1, f2, f3, rois, out);
}

// round 6
// speedup vs baseline: 2.6502x; 2.6502x over previous
#include <cuda_runtime.h>
#include <cuda_bf16.h>

// SingleRoIExtractor: FPN RoIAlign (aligned=False), out 7x7, sr=2.
// R5: R3 (shared geometry) with conflict-free SoA [sample][bin] layout:
// lanes read consecutive int4/float4 -> perfect LDS.128, no bank conflicts.

#define OUTS   7
#define CH     256
#define BINS   (OUTS * OUTS)            // 49
#define PER_ROI (CH * BINS)             // 12544
#define BLK    256
#define BLOCKS_PER_ROI (PER_ROI / BLK)  // 49
#define NSAMPLES 196                    // 4 * 49

__global__ void __launch_bounds__(BLK)
roi_extract_kernel(const float* __restrict__ f0,
                   const float* __restrict__ f1,
                   const float* __restrict__ f2,
                   const float* __restrict__ f3,
                   const float* __restrict__ rois,
                   float* __restrict__ out)
{
    __shared__ int4   s_offs[4][BINS];
    __shared__ float4 s_wts [4][BINS];
    __shared__ float s_x1, s_y1, s_binw, s_binh;
    __shared__ const float* s_base;
    __shared__ int s_H, s_W;

    const int n   = blockIdx.x / BLOCKS_PER_ROI;
    const int blk = blockIdx.x % BLOCKS_PER_ROI;
    const int t   = threadIdx.x;

    if (t == 0) {
        const float rb  = rois[n * 5 + 0];
        const float rx1 = rois[n * 5 + 1];
        const float ry1 = rois[n * 5 + 2];
        const float rx2 = rois[n * 5 + 3];
        const float ry2 = rois[n * 5 + 4];

        const float sc = sqrtf((rx2 - rx1 + 1.0f) * (ry2 - ry1 + 1.0f));
        int lvl = (int)floorf(log2f(sc * (1.0f / 56.0f) + 1e-6f));
        lvl = lvl < 0 ? 0 : (lvl > 3 ? 3 : lvl);

        const float* f; int H, W; float ss;
        if      (lvl == 0) { f = f0; H = 200; W = 304; ss = 0.25f;    }
        else if (lvl == 1) { f = f1; H = 100; W = 152; ss = 0.125f;   }
        else if (lvl == 2) { f = f2; H = 50;  W = 76;  ss = 0.0625f;  }
        else               { f = f3; H = 25;  W = 38;  ss = 0.03125f; }

        const int b = (int)rb;
        const float x1 = rx1 * ss, y1 = ry1 * ss;
        s_x1 = x1; s_y1 = y1;
        s_binw = fmaxf(rx2 * ss - x1, 1.0f) * (1.0f / OUTS);
        s_binh = fmaxf(ry2 * ss - y1, 1.0f) * (1.0f / OUTS);
        s_base = f + (size_t)b * CH * H * W;
        s_H = H; s_W = W;
    }
    __syncthreads();

    if (t < NSAMPLES) {
        const int s   = t >> 6;          // any bijection onto (s,bin) works;
        const int r   = t & 63;          // use t = s*64 + r, r<49 pattern? no:
        // simple: sample-major with bin = t % 49, s = t / 49
        const int ss2 = t / BINS;
        const int bin = t - ss2 * BINS;
        (void)s; (void)r;
        const int ph  = bin / OUTS;
        const int pw  = bin - ph * OUTS;
        const int iy  = ss2 >> 1;
        const int ix  = ss2 & 1;

        const int H = s_H, W = s_W;
        const float Hf = (float)H, Wf = (float)W;

        const float y = s_y1 + ((float)(ph * 2 + iy) + 0.5f) * 0.5f * s_binh;
        const float x = s_x1 + ((float)(pw * 2 + ix) + 0.5f) * 0.5f * s_binw;
        const bool valid = (y >= -1.0f) & (y <= Hf) & (x >= -1.0f) & (x <= Wf);

        const float yc = fminf(fmaxf(y, 0.0f), Hf - 1.0f);
        const float xc = fminf(fmaxf(x, 0.0f), Wf - 1.0f);
        const int   y0 = (int)yc;
        const int   x0 = (int)xc;
        const float ly = yc - (float)y0;
        const float lx = xc - (float)x0;
        const int   yB = min(y0 + 1, H - 1);
        const int   xB = min(x0 + 1, W - 1);

        const float vmul = valid ? 0.25f : 0.0f;   // fold 1/4 sample mean
        const float wy0 = (1.0f - ly) * vmul;
        const float wy1 = ly * vmul;

        s_offs[ss2][bin] = make_int4(y0 * W + x0, y0 * W + xB,
                                     yB * W + x0, yB * W + xB);
        s_wts [ss2][bin] = make_float4(wy0 * (1.0f - lx), wy0 * lx,
                                       wy1 * (1.0f - lx), wy1 * lx);
    }
    __syncthreads();

    const int local = blk * BLK + t;
    const int c   = local / BINS;
    const int bin = local - c * BINS;

    const int HW = s_H * s_W;
    const float* __restrict__ fc = s_base + (size_t)c * HW;

    float acc = 0.0f;
    #pragma unroll
    for (int s = 0; s < 4; ++s) {
        const int4   o = s_offs[s][bin];   // lanes: consecutive 16B -> no conflicts
        const float4 w = s_wts [s][bin];
        acc += __ldg(fc + o.x) * w.x
             + __ldg(fc + o.y) * w.y
             + __ldg(fc + o.z) * w.z
             + __ldg(fc + o.w) * w.w;
    }

    __stcs(out + (size_t)n * PER_ROI + local, acc);
}

extern "C" void kernel_launch(void* const* d_in, const int* in_sizes, int n_in,
                              void* d_out, int out_size)
{
    const float* f0   = (const float*)d_in[0];
    const float* f1   = (const float*)d_in[1];
    const float* f2   = (const float*)d_in[2];
    const float* f3   = (const float*)d_in[3];
    const float* rois = (const float*)d_in[4];
    float* out = (float*)d_out;

    const int K = in_sizes[4] / 5;
    roi_extract_kernel<<<K * BLOCKS_PER_ROI, BLK>>>(f0, f1, f2, f3, rois, out);
}

// round 7
// speedup vs baseline: 3.7061x; 1.3984x over previous
#include <cuda_runtime.h>
#include <cuda_bf16.h>

// SingleRoIExtractor: FPN RoIAlign (aligned=False), out 7x7, sr=2.
// R6: geometry in registers (computed once per thread, branchless),
// amortized over 4 channels per thread. No shared/LDS in hot path.
// Thread = (roi, c0 in [0,64), bin); channels c0 + 64*j, j=0..3.

#define OUTS   7
#define CH     256
#define BINS   (OUTS * OUTS)            // 49
#define PER_ROI (CH * BINS)             // 12544
#define CPT    4                        // channels per thread
#define CGRP   (CH / CPT)               // 64 base channels
#define THR_PER_ROI (CGRP * BINS)       // 3136
#define BLK    224                      // 3136 / 224 = 14 blocks per RoI
#define BLOCKS_PER_ROI (THR_PER_ROI / BLK)

__global__ void __launch_bounds__(BLK)
roi_extract_kernel(const float* __restrict__ f0,
                   const float* __restrict__ f1,
                   const float* __restrict__ f2,
                   const float* __restrict__ f3,
                   const float* __restrict__ rois,
                   float* __restrict__ out)
{
    const int n     = blockIdx.x / BLOCKS_PER_ROI;
    const int blk   = blockIdx.x % BLOCKS_PER_ROI;
    const int local = blk * BLK + threadIdx.x;      // [0, 3136)
    const int c0    = local / BINS;                 // [0, 64)
    const int bin   = local - c0 * BINS;            // [0, 49)
    const int ph    = bin / OUTS;
    const int pw    = bin - ph * OUTS;

    // ---- per-RoI params (L1-broadcast across the block) ----
    const float rb  = __ldg(rois + n * 5 + 0);
    const float rx1 = __ldg(rois + n * 5 + 1);
    const float ry1 = __ldg(rois + n * 5 + 2);
    const float rx2 = __ldg(rois + n * 5 + 3);
    const float ry2 = __ldg(rois + n * 5 + 4);

    const float sc = sqrtf((rx2 - rx1 + 1.0f) * (ry2 - ry1 + 1.0f));
    int lvl = (int)floorf(log2f(sc * (1.0f / 56.0f) + 1e-6f));
    lvl = lvl < 0 ? 0 : (lvl > 3 ? 3 : lvl);

    const float* f; int H, W; float ss;
    if      (lvl == 0) { f = f0; H = 200; W = 304; ss = 0.25f;    }
    else if (lvl == 1) { f = f1; H = 100; W = 152; ss = 0.125f;   }
    else if (lvl == 2) { f = f2; H = 50;  W = 76;  ss = 0.0625f;  }
    else               { f = f3; H = 25;  W = 38;  ss = 0.03125f; }

    const int   b    = (int)rb;
    const int   HW   = H * W;
    const float x1   = rx1 * ss, y1 = ry1 * ss;
    const float binw = fmaxf(rx2 * ss - x1, 1.0f) * (1.0f / OUTS);
    const float binh = fmaxf(ry2 * ss - y1, 1.0f) * (1.0f / OUTS);
    const float Hf = (float)H, Wf = (float)W;

    // ---- geometry for the 4 samples of this bin, once, in registers ----
    int   o00[4], o01[4], o10[4], o11[4];
    float w00[4], w01[4], w10[4], w11[4];

    #pragma unroll
    for (int s = 0; s < 4; ++s) {
        const int iy = s >> 1, ix = s & 1;
        const float y = y1 + ((float)(ph * 2 + iy) + 0.5f) * 0.5f * binh;
        const float x = x1 + ((float)(pw * 2 + ix) + 0.5f) * 0.5f * binw;
        const bool valid = (y >= -1.0f) & (y <= Hf) & (x >= -1.0f) & (x <= Wf);

        const float yc = fminf(fmaxf(y, 0.0f), Hf - 1.0f);
        const float xc = fminf(fmaxf(x, 0.0f), Wf - 1.0f);
        const int   yi = (int)yc;
        const int   xi = (int)xc;
        const float ly = yc - (float)yi;
        const float lx = xc - (float)xi;
        const int   yB = min(yi + 1, H - 1);
        const int   xB = min(xi + 1, W - 1);

        const float vmul = valid ? 0.25f : 0.0f;    // fold 1/4 sample mean
        const float wy0 = (1.0f - ly) * vmul;
        const float wy1 = ly * vmul;

        o00[s] = yi * W + xi;  o01[s] = yi * W + xB;
        o10[s] = yB * W + xi;  o11[s] = yB * W + xB;
        w00[s] = wy0 * (1.0f - lx);  w01[s] = wy0 * lx;
        w10[s] = wy1 * (1.0f - lx);  w11[s] = wy1 * lx;
    }

    // ---- 4 channels per thread: pure LDG + FFMA + STG ----
    const float* __restrict__ base = f + (size_t)b * CH * HW + (size_t)c0 * HW;
    float* __restrict__ po = out + (size_t)n * PER_ROI + (size_t)c0 * BINS + bin;
    const size_t cstep = (size_t)CGRP * HW;          // 64 channel planes
    const size_t ostep = (size_t)CGRP * BINS;

    #pragma unroll
    for (int j = 0; j < CPT; ++j) {
        const float* __restrict__ fc = base + j * cstep;
        float acc = 0.0f;
        #pragma unroll
        for (int s = 0; s < 4; ++s) {
            acc += __ldg(fc + o00[s]) * w00[s]
                 + __ldg(fc + o01[s]) * w01[s]
                 + __ldg(fc + o10[s]) * w10[s]
                 + __ldg(fc + o11[s]) * w11[s];
        }
        __stcs(po + j * ostep, acc);
    }
}

extern "C" void kernel_launch(void* const* d_in, const int* in_sizes, int n_in,
                              void* d_out, int out_size)
{
    const float* f0   = (const float*)d_in[0];
    const float* f1   = (const float*)d_in[1];
    const float* f2   = (const float*)d_in[2];
    const float* f3   = (const float*)d_in[3];
    const float* rois = (const float*)d_in[4];
    float* out = (float*)d_out;

    const int K = in_sizes[4] / 5;
    roi_extract_kernel<<<K * BLOCKS_PER_ROI, BLK>>>(f0, f1, f2, f3, rois, out);
}